// round 1
// baseline (speedup 1.0000x reference)
#include <cuda_runtime.h>

// Problem constants (fixed by setup_inputs):
//   rgb: (1, 3, 2048, 2048) fp32; num_bins=4, kernel_size=3, pixel_size=32
#define H       2048
#define W       2048
#define PS      32          // pixel_size (conv stride)
#define OB      (H / PS)    // 64 output cells per dim
#define NB      4           // num_bins
#define PLANE   (H * W)     // elements per channel

__global__ __launch_bounds__(256)
void pixel_effect_kernel(const float* __restrict__ rgb, float* __restrict__ out) {
    const int blk = blockIdx.x;        // 0 .. OB*OB-1
    const int ow  = blk & (OB - 1);
    const int oh  = blk >> 6;

    __shared__ float s_col[3];

    if (threadIdx.x == 0) {
        // 3x3 window centered at (oh*PS, ow*PS), zero-padded (skip OOB: padded
        // pixels have mask==0 in the reference, contributing nothing).
        float sumc[3][NB];
        int   cnt[NB];
        #pragma unroll
        for (int b = 0; b < NB; b++) { cnt[b] = 0; sumc[0][b] = 0.f; sumc[1][b] = 0.f; sumc[2][b] = 0.f; }

        const int hc = oh * PS, wc = ow * PS;
        #pragma unroll
        for (int dh = -1; dh <= 1; dh++) {
            const int h = hc + dh;
            if (h < 0 || h >= H) continue;
            #pragma unroll
            for (int dw = -1; dw <= 1; dw++) {
                const int w = wc + dw;
                if (w < 0 || w >= W) continue;
                const float* p = rgb + (size_t)h * W + w;
                const float r = p[0];
                const float g = p[PLANE];
                const float b = p[2 * PLANE];
                // bin = int( ((r+g+b)/3) / 256 * 4 ), IEEE ops to match JAX exactly
                const float s    = __fadd_rn(__fadd_rn(r, g), b);
                const float mean = __fdiv_rn(s, 3.0f);
                const float v    = __fmul_rn(__fdiv_rn(mean, 256.0f), 4.0f);
                int bin = (int)v;                     // truncation (values >= 0)
                if (bin > NB - 1) bin = NB - 1;        // safety clamp
                cnt[bin] += 1;
                sumc[0][bin] += r;
                sumc[1][bin] += g;
                sumc[2][bin] += b;
            }
        }

        // argmax over bins, first-max tie-break (matches jnp.argmax)
        int best = 0;
        #pragma unroll
        for (int b = 1; b < NB; b++) if (cnt[b] > cnt[best]) best = b;

        const float imax = (float)cnt[best];
        s_col[0] = __fdiv_rn(sumc[0][best], imax);
        s_col[1] = __fdiv_rn(sumc[1][best], imax);
        s_col[2] = __fdiv_rn(sumc[2][best], imax);
    }
    __syncthreads();

    const float r = s_col[0];
    const float g = s_col[1];
    const float b = s_col[2];

    // Broadcast-fill the 32x32 block in all 3 channel planes.
    // 256 threads: thread t -> row = t/8, float4-column = t%8 (32 rows x 8 float4 = 256)
    const int t    = threadIdx.x;
    const int row  = t >> 3;
    const int c4   = t & 7;
    const size_t base = (size_t)(oh * PS + row) * W + (size_t)ow * PS + (size_t)c4 * 4;

    float4* o0 = reinterpret_cast<float4*>(out + base);
    float4* o1 = reinterpret_cast<float4*>(out + base + (size_t)PLANE);
    float4* o2 = reinterpret_cast<float4*>(out + base + (size_t)2 * PLANE);
    *o0 = make_float4(r, r, r, r);
    *o1 = make_float4(g, g, g, g);
    *o2 = make_float4(b, b, b, b);
}

extern "C" void kernel_launch(void* const* d_in, const int* in_sizes, int n_in,
                              void* d_out, int out_size) {
    const float* rgb = (const float*)d_in[0];
    float* out = (float*)d_out;
    pixel_effect_kernel<<<OB * OB, 256>>>(rgb, out);
}

// round 2
// speedup vs baseline: 1.2534x; 1.2534x over previous
#include <cuda_runtime.h>

// Problem constants (fixed by setup_inputs):
//   rgb: (1, 3, 2048, 2048) fp32; num_bins=4, kernel_size=3, pixel_size=32
#define H       2048
#define W       2048
#define PS      32          // pixel_size (conv stride)
#define OB      (H / PS)    // 64 output cells per dim
#define NB      4           // num_bins
#define PLANE   (H * W)     // elements per channel

// 64x64 cell colors, 3 channels: [ch][oh][ow]
__device__ float g_table[3 * OB * OB];

// ---------------------------------------------------------------------------
// Kernel A: compute per-cell color (4096 cells, 1 thread/cell, 32 thr/block
// so the work spreads across ~128 SMs with high load-MLP per warp).
// ---------------------------------------------------------------------------
__global__ __launch_bounds__(32)
void cell_color_kernel(const float* __restrict__ rgb) {
    const int cell = blockIdx.x * 32 + threadIdx.x;   // 0 .. 4095
    const int ow = cell & (OB - 1);
    const int oh = cell >> 6;

    float sumc[3][NB];
    int   cnt[NB];
    #pragma unroll
    for (int b = 0; b < NB; b++) { cnt[b] = 0; sumc[0][b] = 0.f; sumc[1][b] = 0.f; sumc[2][b] = 0.f; }

    const int hc = oh * PS, wc = ow * PS;
    #pragma unroll
    for (int dh = -1; dh <= 1; dh++) {
        const int h = hc + dh;
        if (h < 0) continue;                 // only low edge can be OOB (max center 2016)
        #pragma unroll
        for (int dw = -1; dw <= 1; dw++) {
            const int w = wc + dw;
            if (w < 0) continue;
            const float* p = rgb + (size_t)h * W + w;
            const float r = __ldg(p);
            const float g = __ldg(p + PLANE);
            const float b = __ldg(p + 2 * PLANE);
            // bin = int( ((r+g+b)/3) / 256 * 4 ), IEEE ops to match JAX exactly
            const float s    = __fadd_rn(__fadd_rn(r, g), b);
            const float mean = __fdiv_rn(s, 3.0f);
            const float v    = __fmul_rn(__fdiv_rn(mean, 256.0f), 4.0f);
            int bin = (int)v;
            if (bin > NB - 1) bin = NB - 1;
            cnt[bin] += 1;
            sumc[0][bin] += r;
            sumc[1][bin] += g;
            sumc[2][bin] += b;
        }
    }

    // argmax over bins, first-max tie-break (matches jnp.argmax)
    int best = 0;
    #pragma unroll
    for (int b = 1; b < NB; b++) if (cnt[b] > cnt[best]) best = b;

    const float imax = (float)cnt[best];
    g_table[0 * OB * OB + cell] = __fdiv_rn(sumc[0][best], imax);
    g_table[1 * OB * OB + cell] = __fdiv_rn(sumc[1][best], imax);
    g_table[2 * OB * OB + cell] = __fdiv_rn(sumc[2][best], imax);
}

// ---------------------------------------------------------------------------
// Kernel B: streaming fill. One block per (channel, row): 2048 floats =
// 512 float4; 256 threads x 2 float4 each. Color fetched directly from the
// table (L1/L2 hit, 8 lanes share an address); no smem, no barrier.
// ---------------------------------------------------------------------------
__global__ __launch_bounds__(256)
void fill_kernel(float* __restrict__ out) {
    const int blk = blockIdx.x;            // 0 .. 3*2048-1
    const int ch  = blk >> 11;             // / 2048
    const int row = blk & (H - 1);
    const int oh  = row >> 5;

    const float* __restrict__ tab = g_table + ch * OB * OB + oh * OB;
    float4* __restrict__ o = reinterpret_cast<float4*>(out + (size_t)ch * PLANE + (size_t)row * W);

    const int t = threadIdx.x;

    const int s0 = t;                      // float4 slot 0..255
    const int s1 = t + 256;                // float4 slot 256..511
    const float c0 = __ldg(tab + (s0 >> 3));   // cell = (s*4)/32 = s/8
    const float c1 = __ldg(tab + (s1 >> 3));

    o[s0] = make_float4(c0, c0, c0, c0);
    o[s1] = make_float4(c1, c1, c1, c1);
}

extern "C" void kernel_launch(void* const* d_in, const int* in_sizes, int n_in,
                              void* d_out, int out_size) {
    const float* rgb = (const float*)d_in[0];
    float* out = (float*)d_out;
    cell_color_kernel<<<OB * OB / 32, 32>>>(rgb);
    fill_kernel<<<3 * H, 256>>>(out);
}

// round 3
// speedup vs baseline: 1.4321x; 1.1425x over previous
#include <cuda_runtime.h>

// rgb: (1, 3, 2048, 2048) fp32; num_bins=4, kernel_size=3, pixel_size=32
#define H       2048
#define W       2048
#define PS      32
#define OB      (H / PS)        // 64
#define NB      4
#define PLANE   (H * W)
#define NCELL   (OB * OB)       // 4096

// cell colors: [ch][cell]
__device__ float g_table[3 * NCELL];

// ---------------------------------------------------------------------------
// Kernel A: one warp per cell. Lanes 0..8 load the 3x3 window (3 parallel
// LDGs each), bin via exact IEEE math, count bins with ballot/popc (exact
// tie-break), warp-sum the winning bin's RGB, lane 0 writes 3 divisions.
// ---------------------------------------------------------------------------
__global__ __launch_bounds__(128)
void cell_color_kernel(const float* __restrict__ rgb) {
    const int cell = blockIdx.x * 4 + (threadIdx.x >> 5);  // 0..4095
    const int lane = threadIdx.x & 31;
    const int ow = cell & (OB - 1);
    const int oh = cell >> 6;

    float r = 0.f, g = 0.f, b = 0.f;
    int bin = -1;

    if (lane < 9) {
        const int dh = lane / 3 - 1;
        const int dw = lane - (lane / 3) * 3 - 1;
        const int h = oh * PS + dh;
        const int w = ow * PS + dw;
        if (h >= 0 && w >= 0) {            // high edge never OOB (max center 2016)
            const float* p = rgb + (size_t)h * W + w;
            r = __ldg(p);
            g = __ldg(p + PLANE);
            b = __ldg(p + 2 * PLANE);
            // bin = int( ((r+g+b)/3) / 256 * 4 ), IEEE ops to match JAX exactly
            const float s    = __fadd_rn(__fadd_rn(r, g), b);
            const float mean = __fdiv_rn(s, 3.0f);
            const float v    = __fmul_rn(__fdiv_rn(mean, 256.0f), 4.0f);
            bin = (int)v;
            if (bin > NB - 1) bin = NB - 1;
        }
    }

    // exact per-bin counts
    const int c0 = __popc(__ballot_sync(0xFFFFFFFFu, bin == 0));
    const int c1 = __popc(__ballot_sync(0xFFFFFFFFu, bin == 1));
    const int c2 = __popc(__ballot_sync(0xFFFFFFFFu, bin == 2));
    const int c3 = __popc(__ballot_sync(0xFFFFFFFFu, bin == 3));

    // argmax, first-max tie-break (matches jnp.argmax)
    int best = 0, bc = c0;
    if (c1 > bc) { best = 1; bc = c1; }
    if (c2 > bc) { best = 2; bc = c2; }
    if (c3 > bc) { best = 3; bc = c3; }

    // sum winning bin's channels across the warp
    float rs = (bin == best) ? r : 0.f;
    float gs = (bin == best) ? g : 0.f;
    float bs = (bin == best) ? b : 0.f;
    #pragma unroll
    for (int off = 16; off > 0; off >>= 1) {
        rs += __shfl_down_sync(0xFFFFFFFFu, rs, off);
        gs += __shfl_down_sync(0xFFFFFFFFu, gs, off);
        bs += __shfl_down_sync(0xFFFFFFFFu, bs, off);
    }

    if (lane == 0) {
        const float imax = (float)bc;
        g_table[0 * NCELL + cell] = __fdiv_rn(rs, imax);
        g_table[1 * NCELL + cell] = __fdiv_rn(gs, imax);
        g_table[2 * NCELL + cell] = __fdiv_rn(bs, imax);
    }
}

// ---------------------------------------------------------------------------
// Kernel B: one block per cell fills 32x32 x 3 channels.
// 3 uniform table loads (broadcast, L1-hit) then 3 independent float4 stores
// per thread. 256 threads: thread t -> row t/8, float4-col t%8.
// ---------------------------------------------------------------------------
__global__ __launch_bounds__(256)
void fill_kernel(float* __restrict__ out) {
    const int cell = blockIdx.x;
    const int ow = cell & (OB - 1);
    const int oh = cell >> 6;

    const float r = __ldg(&g_table[0 * NCELL + cell]);
    const float g = __ldg(&g_table[1 * NCELL + cell]);
    const float b = __ldg(&g_table[2 * NCELL + cell]);

    const int t   = threadIdx.x;
    const int row = t >> 3;
    const int c4  = t & 7;
    const size_t base = (size_t)(oh * PS + row) * W + (size_t)ow * PS + (size_t)c4 * 4;

    float4* o0 = reinterpret_cast<float4*>(out + base);
    float4* o1 = reinterpret_cast<float4*>(out + base + (size_t)PLANE);
    float4* o2 = reinterpret_cast<float4*>(out + base + (size_t)2 * PLANE);
    *o0 = make_float4(r, r, r, r);
    *o1 = make_float4(g, g, g, g);
    *o2 = make_float4(b, b, b, b);
}

extern "C" void kernel_launch(void* const* d_in, const int* in_sizes, int n_in,
                              void* d_out, int out_size) {
    const float* rgb = (const float*)d_in[0];
    float* out = (float*)d_out;
    cell_color_kernel<<<NCELL / 4, 128>>>(rgb);
    fill_kernel<<<NCELL, 256>>>(out);
}

// round 4
// speedup vs baseline: 1.5760x; 1.1005x over previous
#include <cuda_runtime.h>

// rgb: (1, 3, 2048, 2048) fp32; num_bins=4, kernel_size=3, pixel_size=32
#define H       2048
#define W       2048
#define PS      32
#define OB      (H / PS)        // 64
#define NB      4
#define PLANE   (H * W)
#define NCELL   (OB * OB)       // 4096

// ---------------------------------------------------------------------------
// Fully fused: one warp per cell, no shared memory, no barriers.
//   1) lanes 0..8 load the 3x3 window (3 parallel LDGs each)
//   2) exact bin via IEEE ops; counts via ballot/popc (exact argmax tie-break)
//   3) butterfly shuffle-reduce -> every lane holds the winning-bin sums
//   4) every lane: 8 rows x 3 channels = 24 independent STG.128
// Lane l covers float4-column (l & 7) and rows (l>>3)*8 .. +7 of the 32x32
// cell: each warp-level store = 4 rows x 8 consecutive float4 = 4 x 128B
// coalesced segments (minimum wavefronts for 512B).
// ---------------------------------------------------------------------------
__global__ __launch_bounds__(256)
void pixel_effect_fused(const float* __restrict__ rgb, float* __restrict__ out) {
    const int warp = blockIdx.x * 8 + (threadIdx.x >> 5);   // 0 .. 4095 (cell id)
    const int lane = threadIdx.x & 31;
    const int ow = warp & (OB - 1);
    const int oh = warp >> 6;

    float r = 0.f, g = 0.f, b = 0.f;
    int bin = -1;

    if (lane < 9) {
        const int dh = lane / 3 - 1;
        const int dw = lane - (lane / 3) * 3 - 1;
        const int h = oh * PS + dh;
        const int w = ow * PS + dw;
        if (h >= 0 && w >= 0) {          // high edge never OOB (max center 2016)
            const float* p = rgb + (size_t)h * W + w;
            r = __ldg(p);
            g = __ldg(p + PLANE);
            b = __ldg(p + 2 * PLANE);
            // bin = int( ((r+g+b)/3) / 256 * 4 ), IEEE ops to match JAX exactly
            const float s    = __fadd_rn(__fadd_rn(r, g), b);
            const float mean = __fdiv_rn(s, 3.0f);
            const float v    = __fmul_rn(__fdiv_rn(mean, 256.0f), 4.0f);
            bin = (int)v;
            if (bin > NB - 1) bin = NB - 1;
        }
    }

    // exact per-bin counts (uniform across warp)
    const int c0 = __popc(__ballot_sync(0xFFFFFFFFu, bin == 0));
    const int c1 = __popc(__ballot_sync(0xFFFFFFFFu, bin == 1));
    const int c2 = __popc(__ballot_sync(0xFFFFFFFFu, bin == 2));
    const int c3 = __popc(__ballot_sync(0xFFFFFFFFu, bin == 3));

    // argmax, first-max tie-break (matches jnp.argmax)
    int best = 0, bc = c0;
    if (c1 > bc) { best = 1; bc = c1; }
    if (c2 > bc) { best = 2; bc = c2; }
    if (c3 > bc) { best = 3; bc = c3; }

    // butterfly reduce: all lanes end with the full sums of the winning bin
    float rs = (bin == best) ? r : 0.f;
    float gs = (bin == best) ? g : 0.f;
    float bs = (bin == best) ? b : 0.f;
    #pragma unroll
    for (int off = 16; off > 0; off >>= 1) {
        rs += __shfl_xor_sync(0xFFFFFFFFu, rs, off);
        gs += __shfl_xor_sync(0xFFFFFFFFu, gs, off);
        bs += __shfl_xor_sync(0xFFFFFFFFu, bs, off);
    }

    const float imax = (float)bc;                 // uniform
    const float cr = __fdiv_rn(rs, imax);
    const float cg = __fdiv_rn(gs, imax);
    const float cb = __fdiv_rn(bs, imax);

    const float4 vr = make_float4(cr, cr, cr, cr);
    const float4 vg = make_float4(cg, cg, cg, cg);
    const float4 vb = make_float4(cb, cb, cb, cb);

    // fill: lane -> col4 = lane&7, rows (lane>>3)*8 .. +7
    const int c4   = lane & 7;
    const int rbase = (lane >> 3) * 8;
    const size_t col0 = (size_t)(oh * PS + rbase) * W + (size_t)ow * PS + (size_t)c4 * 4;

    float* p0 = out + col0;
    #pragma unroll
    for (int i = 0; i < 8; i++) {
        float* p = p0 + (size_t)i * W;
        *reinterpret_cast<float4*>(p)                       = vr;
        *reinterpret_cast<float4*>(p + (size_t)PLANE)       = vg;
        *reinterpret_cast<float4*>(p + (size_t)2 * PLANE)   = vb;
    }
}

extern "C" void kernel_launch(void* const* d_in, const int* in_sizes, int n_in,
                              void* d_out, int out_size) {
    const float* rgb = (const float*)d_in[0];
    float* out = (float*)d_out;
    pixel_effect_fused<<<NCELL / 8, 256>>>(rgb, out);
}

// round 5
// speedup vs baseline: 1.5877x; 1.0074x over previous
#include <cuda_runtime.h>

// rgb: (1, 3, 2048, 2048) fp32; num_bins=4, kernel_size=3, pixel_size=32
#define H       2048
#define W       2048
#define PS      32
#define OB      (H / PS)        // 64
#define NB      4
#define PLANE   (H * W)
#define NCELL   (OB * OB)       // 4096

// ---------------------------------------------------------------------------
// Fused, 4 warps per cell (cell x quadrant). Each warp independently:
//   1) lanes 0..8 load the 3x3 window (3 parallel LDGs each)
//   2) exact bin via IEEE ops; counts via ballot/popc (exact argmax tie-break)
//   3) butterfly shuffle-reduce -> every lane holds winning-bin sums
//   4) stores its 8-row quadrant: 2 rows x 3 channels = 6 independent STG.128
// Redundant color compute (x4) costs ~1.8MB of reads total (trivial) but
// removes all inter-warp dependencies and quadruples store-issue parallelism.
// Warp store = lanes 0-7 row r, 8-15 r+2, 16-23 r+4, 24-31 r+6: 4 x 128B
// coalesced segments per STG.
// ---------------------------------------------------------------------------
__global__ __launch_bounds__(512)
void pixel_effect_fused(const float* __restrict__ rgb, float* __restrict__ out) {
    const int gwarp = blockIdx.x * 16 + (threadIdx.x >> 5);  // 0 .. 16383
    const int lane  = threadIdx.x & 31;
    const int cell  = gwarp >> 2;        // 0 .. 4095
    const int quad  = gwarp & 3;         // row quadrant 0..3
    const int ow = cell & (OB - 1);
    const int oh = cell >> 6;

    float r = 0.f, g = 0.f, b = 0.f;
    int bin = -1;

    if (lane < 9) {
        const int dh = lane / 3 - 1;
        const int dw = lane - (lane / 3) * 3 - 1;
        const int h = oh * PS + dh;
        const int w = ow * PS + dw;
        if (h >= 0 && w >= 0) {          // high edge never OOB (max center 2016)
            const float* p = rgb + (size_t)h * W + w;
            r = __ldg(p);
            g = __ldg(p + PLANE);
            b = __ldg(p + 2 * PLANE);
            // bin = int( ((r+g+b)/3) / 256 * 4 ), IEEE ops to match JAX exactly
            const float s    = __fadd_rn(__fadd_rn(r, g), b);
            const float mean = __fdiv_rn(s, 3.0f);
            const float v    = __fmul_rn(__fdiv_rn(mean, 256.0f), 4.0f);
            bin = (int)v;
            if (bin > NB - 1) bin = NB - 1;
        }
    }

    // exact per-bin counts (uniform across warp)
    const int c0 = __popc(__ballot_sync(0xFFFFFFFFu, bin == 0));
    const int c1 = __popc(__ballot_sync(0xFFFFFFFFu, bin == 1));
    const int c2 = __popc(__ballot_sync(0xFFFFFFFFu, bin == 2));
    const int c3 = __popc(__ballot_sync(0xFFFFFFFFu, bin == 3));

    // argmax, first-max tie-break (matches jnp.argmax)
    int best = 0, bc = c0;
    if (c1 > bc) { best = 1; bc = c1; }
    if (c2 > bc) { best = 2; bc = c2; }
    if (c3 > bc) { best = 3; bc = c3; }

    // butterfly reduce: all lanes end with the winning bin's sums
    float rs = (bin == best) ? r : 0.f;
    float gs = (bin == best) ? g : 0.f;
    float bs = (bin == best) ? b : 0.f;
    #pragma unroll
    for (int off = 16; off > 0; off >>= 1) {
        rs += __shfl_xor_sync(0xFFFFFFFFu, rs, off);
        gs += __shfl_xor_sync(0xFFFFFFFFu, gs, off);
        bs += __shfl_xor_sync(0xFFFFFFFFu, bs, off);
    }

    const float imax = (float)bc;                 // uniform
    const float cr = __fdiv_rn(rs, imax);
    const float cg = __fdiv_rn(gs, imax);
    const float cb = __fdiv_rn(bs, imax);

    const float4 vr = make_float4(cr, cr, cr, cr);
    const float4 vg = make_float4(cg, cg, cg, cg);
    const float4 vb = make_float4(cb, cb, cb, cb);

    // quadrant fill: lane -> col4 = lane&7, rows quad*8 + (lane>>3)*2 + {0,1}
    const int c4    = lane & 7;
    const int rbase = quad * 8 + (lane >> 3) * 2;
    const size_t base = (size_t)(oh * PS + rbase) * W + (size_t)ow * PS + (size_t)c4 * 4;

    float* p0 = out + base;
    float* p1 = p0 + W;
    *reinterpret_cast<float4*>(p0)                     = vr;
    *reinterpret_cast<float4*>(p0 + (size_t)PLANE)     = vg;
    *reinterpret_cast<float4*>(p0 + (size_t)2 * PLANE) = vb;
    *reinterpret_cast<float4*>(p1)                     = vr;
    *reinterpret_cast<float4*>(p1 + (size_t)PLANE)     = vg;
    *reinterpret_cast<float4*>(p1 + (size_t)2 * PLANE) = vb;
}

extern "C" void kernel_launch(void* const* d_in, const int* in_sizes, int n_in,
                              void* d_out, int out_size) {
    const float* rgb = (const float*)d_in[0];
    float* out = (float*)d_out;
    pixel_effect_fused<<<NCELL * 4 / 16, 512>>>(rgb, out);
}